// round 1
// baseline (speedup 1.0000x reference)
#include <cuda_runtime.h>

#define S_LEN  2048
#define HQ     16
#define HKV    2
#define GQA    8
#define DIM    64
#define CSTRIDE 16
#define LC     32
#define LB     64
#define KSEL   8
#define WIN    512
#define SC_N   127     // compressed sequence length: (2048-32)/16 + 1
#define NBLK   32
#define NOUT   31
#define SCALE  0.125f  // 64^-0.5
#define NTHREADS 256

// scratch (no allocations allowed)
__device__ float g_ck[HKV * SC_N * DIM];
__device__ float g_cv[HKV * SC_N * DIM];

// ---------------------------------------------------------------------------
// Kernel A: conv1d compressor  ck[h][c][o] = sum_{i,t} k[c*16+t][h][i]*wk[o][i][t]
// ---------------------------------------------------------------------------
__global__ void __launch_bounds__(256) compress_kernel(
    const float* __restrict__ k, const float* __restrict__ v,
    const float* __restrict__ wk, const float* __restrict__ wv)
{
    const int b   = blockIdx.x;       // hkv*SC_N + c
    const int hkv = b / SC_N;
    const int c   = b % SC_N;
    __shared__ float ks[LC][DIM];
    __shared__ float vs[LC][DIM];
    __shared__ float red[4][DIM];
    const int tid = threadIdx.x;

    for (int idx = tid; idx < LC * DIM; idx += NTHREADS) {
        int t = idx / DIM, i = idx % DIM;
        int pos = c * CSTRIDE + t;
        ks[t][i] = k[(pos * HKV + hkv) * DIM + i];
        vs[t][i] = v[(pos * HKV + hkv) * DIM + i];
    }
    __syncthreads();

    const int o    = tid & 63;
    const int part = tid >> 6;            // 0..3, covers i in [part*16, part*16+16)
    float ak0 = 0.f, ak1 = 0.f, av0 = 0.f, av1 = 0.f;
    for (int i = part * 16; i < part * 16 + 16; ++i) {
        const float4* wk4 = reinterpret_cast<const float4*>(wk + (o * DIM + i) * LC);
        const float4* wv4 = reinterpret_cast<const float4*>(wv + (o * DIM + i) * LC);
        #pragma unroll
        for (int t4 = 0; t4 < 8; ++t4) {
            float4 a = __ldg(&wk4[t4]);
            float4 bw = __ldg(&wv4[t4]);
            int t = t4 * 4;
            float pk = a.x * ks[t][i] + a.y * ks[t + 1][i]
                     + a.z * ks[t + 2][i] + a.w * ks[t + 3][i];
            float pv = bw.x * vs[t][i] + bw.y * vs[t + 1][i]
                     + bw.z * vs[t + 2][i] + bw.w * vs[t + 3][i];
            if (t4 & 1) { ak1 += pk; av1 += pv; } else { ak0 += pk; av0 += pv; }
        }
    }
    red[part][o] = ak0 + ak1;
    __syncthreads();
    if (part == 0)
        g_ck[(hkv * SC_N + c) * DIM + o] = red[0][o] + red[1][o] + red[2][o] + red[3][o];
    __syncthreads();
    red[part][o] = av0 + av1;
    __syncthreads();
    if (part == 0)
        g_cv[(hkv * SC_N + c) * DIM + o] = red[0][o] + red[1][o] + red[2][o] + red[3][o];
}

// ---------------------------------------------------------------------------
// Mega kernel: one block per (hkv, s). 256 threads.
// ---------------------------------------------------------------------------
extern __shared__ float smem[];

__global__ void __launch_bounds__(256) nsa_mega_kernel(
    const float* __restrict__ q, const float* __restrict__ k,
    const float* __restrict__ v, const float* __restrict__ wg,
    float* __restrict__ out)
{
    const int bx   = blockIdx.x;
    const int s    = bx >> 1;
    const int hkv  = bx & 1;
    const int tid  = threadIdx.x;
    const int lane = tid & 31;
    const int wid  = tid >> 5;

    // smem carve
    float* q_s   = smem;                   // [8][64]
    float* sc    = q_s + 8 * 64;           // [8][512] (cmp uses [8][128] view)
    float* kv    = sc + 8 * 512;           // [64][68] padded tile
    float* red   = kv + 64 * 68;           // [16][512]
    float* o_acc = red + 16 * 512;         // [8][64]
    float* pkv   = o_acc + 8 * 64;         // [128]
    float* gsm   = pkv + 128;              // [8][3]
    int*   selblk = (int*)(gsm + 24);      // [8]

    // ---- load q tile, zero cmp score region ----
    for (int i = tid; i < 512; i += NTHREADS) {
        int h = i >> 6, d = i & 63;
        q_s[i] = q[(s * HQ + hkv * GQA + h) * DIM + d];
    }
    for (int i = tid; i < 8 * 128; i += NTHREADS) sc[i] = 0.f;
    __syncthreads();

    // ---- gates (linear, no bias) ----
    if (tid < 24) {
        int h = tid / 3, e = tid % 3;
        float a = 0.f;
        for (int d = 0; d < DIM; ++d) a += q_s[h * 64 + d] * wg[e * DIM + d];
        gsm[h * 3 + e] = a;
    }

    // ---- branch 3: compressed attention scores ----
    const int Nc = (s >= 31) ? (((s - 31) >> 4) + 1) : 0;
    for (int idx = tid; idx < 8 * Nc; idx += NTHREADS) {
        int c = idx >> 3, h = idx & 7;
        const float4* ck4 = reinterpret_cast<const float4*>(g_ck + (hkv * SC_N + c) * DIM);
        const float4* q4  = reinterpret_cast<const float4*>(q_s + h * 64);
        float a0 = 0, a1 = 0, a2 = 0, a3 = 0;
        #pragma unroll
        for (int i = 0; i < 16; ++i) {
            float4 a = __ldg(&ck4[i]); float4 b = q4[i];
            a0 += a.x * b.x; a1 += a.y * b.y; a2 += a.z * b.z; a3 += a.w * b.w;
        }
        sc[h * 128 + c] = (a0 + a1 + a2 + a3) * SCALE;
    }
    __syncthreads();

    // ---- cmp softmax: warp per head ----
    {
        int h = wid;
        float vals[4];
        float m = -1e30f;
        #pragma unroll
        for (int r = 0; r < 4; ++r) {
            int c = lane + r * 32;
            vals[r] = (c < Nc) ? sc[h * 128 + c] : -1e30f;
            m = fmaxf(m, vals[r]);
        }
        #pragma unroll
        for (int off = 16; off; off >>= 1) m = fmaxf(m, __shfl_xor_sync(~0u, m, off));
        float sum = 0.f;
        #pragma unroll
        for (int r = 0; r < 4; ++r) {
            int c = lane + r * 32;
            float p = (c < Nc) ? expf(vals[r] - m) : 0.f;
            vals[r] = p; sum += p;
        }
        #pragma unroll
        for (int off = 16; off; off >>= 1) sum += __shfl_xor_sync(~0u, sum, off);
        float inv = (Nc > 0) ? (1.f / sum) : 0.f;
        #pragma unroll
        for (int r = 0; r < 4; ++r) {
            int c = lane + r * 32;
            sc[h * 128 + c] = vals[r] * inv;   // masked/unused c stay exactly 0
        }
    }
    __syncthreads();

    // ---- p_kv = sum over heads ----
    if (tid < 128) {
        float a = 0.f;
        #pragma unroll
        for (int h = 0; h < 8; ++h) a += sc[h * 128 + tid];
        pkv[tid] = a;
    }
    __syncthreads();

    // ---- cmp output -> o_acc = g2 * cmp ----
    #pragma unroll
    for (int it = 0; it < 2; ++it) {
        int item = tid + it * NTHREADS;
        int h = item >> 6, d = item & 63;
        float a0 = 0.f, a1 = 0.f;
        int c = 0;
        for (; c + 1 < Nc; c += 2) {
            a0 += sc[h * 128 + c]     * __ldg(g_cv + (hkv * SC_N + c) * DIM + d);
            a1 += sc[h * 128 + c + 1] * __ldg(g_cv + (hkv * SC_N + c + 1) * DIM + d);
        }
        if (c < Nc) a0 += sc[h * 128 + c] * __ldg(g_cv + (hkv * SC_N + c) * DIM + d);
        o_acc[item] = gsm[h * 3 + 2] * (a0 + a1);
    }

    // ---- pooling + top-8 block selection (warp 0) ----
    if (wid == 0) {
        float myval;
        if (lane < NOUT) {
            float a = pkv[lane * 4] + pkv[lane * 4 + 1] + pkv[lane * 4 + 2]
                    + pkv[lane * 4 + 3] + pkv[lane * 4 + 4];
            myval = a / 5.0f;
        } else {
            myval = -1.0f;
        }
        if (lane == (s >> 6)) myval = __int_as_float(0x7f800000);  // +inf: forced block
        #pragma unroll
        for (int r = 0; r < KSEL; ++r) {
            float bv = myval; int bi = lane;
            #pragma unroll
            for (int off = 16; off; off >>= 1) {
                float ov = __shfl_xor_sync(~0u, bv, off);
                int   oi = __shfl_xor_sync(~0u, bi, off);
                if (ov > bv || (ov == bv && oi < bi)) { bv = ov; bi = oi; }
            }
            if (lane == 0) selblk[r] = bi;
            if (lane == bi) myval = __int_as_float(0xff800000);    // -inf: remove
        }
    }
    __syncthreads();

    // ---- branches: 0 = selection (gather), 1 = sliding window ----
    const int my_d4 = tid & 15;
    const int my_jg = tid >> 4;

    #pragma unroll 1
    for (int br = 0; br < 2; ++br) {
        int T, lo = 0;
        if (br == 0) {
            T = 8;
        } else {
            lo = (s >= WIN) ? s - WIN + 1 : 0;
            int n = s - lo + 1;
            T = (n + 63) >> 6;
        }
        const int nj = T * 64;

        // pass 1: scores
        for (int tt = 0; tt < T; ++tt) {
            int base = (br == 0) ? selblk[tt] * LB : lo + tt * 64;
            {   // stage 64 K rows, padded rows of 68 floats
                int jj = tid >> 2, part = tid & 3;
                int pos = base + jj;
                const float4* krow = reinterpret_cast<const float4*>(k + (pos * HKV + hkv) * DIM);
                float4* dst = reinterpret_cast<float4*>(kv + jj * 68 + part * 16);
                #pragma unroll
                for (int r = 0; r < 4; ++r) dst[r] = __ldg(&krow[part * 4 + r]);
            }
            __syncthreads();
            #pragma unroll
            for (int it = 0; it < 2; ++it) {
                int idx = tid + it * NTHREADS;
                int h = idx >> 6, jj = idx & 63;
                const float4* q4 = reinterpret_cast<const float4*>(q_s + h * 64);
                const float4* k4 = reinterpret_cast<const float4*>(kv + jj * 68);
                float a0 = 0, a1 = 0, a2 = 0, a3 = 0;
                #pragma unroll
                for (int i = 0; i < 16; ++i) {
                    float4 a = q4[i]; float4 b = k4[i];
                    a0 += a.x * b.x; a1 += a.y * b.y; a2 += a.z * b.z; a3 += a.w * b.w;
                }
                int pos = base + jj;
                sc[h * 512 + tt * 64 + jj] =
                    (pos <= s) ? (a0 + a1 + a2 + a3) * SCALE : -1e30f;
            }
            __syncthreads();
        }

        // softmax over nj keys, warp per head
        {
            int h = wid;
            float m = -1e30f;
            for (int j = lane; j < nj; j += 32) m = fmaxf(m, sc[h * 512 + j]);
            #pragma unroll
            for (int off = 16; off; off >>= 1) m = fmaxf(m, __shfl_xor_sync(~0u, m, off));
            float sum = 0.f;
            for (int j = lane; j < nj; j += 32) {
                float p = expf(sc[h * 512 + j] - m);
                sc[h * 512 + j] = p;
                sum += p;
            }
            #pragma unroll
            for (int off = 16; off; off >>= 1) sum += __shfl_xor_sync(~0u, sum, off);
            float inv = 1.f / sum;
            for (int j = lane; j < nj; j += 32) sc[h * 512 + j] *= inv;
        }
        __syncthreads();

        // pass 2: PV. thread = (jg, d4); acc over 8 heads x 4 dims
        float acc[8][4];
        #pragma unroll
        for (int h = 0; h < 8; ++h)
            acc[h][0] = acc[h][1] = acc[h][2] = acc[h][3] = 0.f;

        for (int tt = 0; tt < T; ++tt) {
            int base = (br == 0) ? selblk[tt] * LB : lo + tt * 64;
            {   // stage 64 V rows
                int jj = tid >> 2, part = tid & 3;
                int pos = base + jj;
                const float4* vrow = reinterpret_cast<const float4*>(v + (pos * HKV + hkv) * DIM);
                float4* dst = reinterpret_cast<float4*>(kv + jj * 68 + part * 16);
                #pragma unroll
                for (int r = 0; r < 4; ++r) dst[r] = __ldg(&vrow[part * 4 + r]);
            }
            __syncthreads();
            #pragma unroll
            for (int jr = 0; jr < 4; ++jr) {
                int jl = my_jg + jr * 16;
                float4 v4 = *reinterpret_cast<const float4*>(kv + jl * 68 + my_d4 * 4);
                int j = tt * 64 + jl;
                #pragma unroll
                for (int h = 0; h < 8; ++h) {
                    float p = sc[h * 512 + j];
                    acc[h][0] += p * v4.x; acc[h][1] += p * v4.y;
                    acc[h][2] += p * v4.z; acc[h][3] += p * v4.w;
                }
            }
            __syncthreads();
        }

        // write partials and reduce 16 j-groups
        #pragma unroll
        for (int h = 0; h < 8; ++h) {
            float4* dst = reinterpret_cast<float4*>(red + my_jg * 512 + h * 64 + my_d4 * 4);
            *dst = make_float4(acc[h][0], acc[h][1], acc[h][2], acc[h][3]);
        }
        __syncthreads();
        #pragma unroll
        for (int it = 0; it < 2; ++it) {
            int item = tid + it * NTHREADS;
            int h = item >> 6;
            float a = 0.f;
            #pragma unroll
            for (int jg = 0; jg < 16; ++jg) a += red[jg * 512 + item];
            o_acc[item] += gsm[h * 3 + br] * a;   // br0 -> gate0(sel), br1 -> gate1(swa)
        }
        __syncthreads();
    }

    // ---- final store ----
    #pragma unroll
    for (int it = 0; it < 2; ++it) {
        int item = tid + it * NTHREADS;
        int h = item >> 6, d = item & 63;
        out[(s * HQ + hkv * GQA + h) * DIM + d] = o_acc[item];
    }
}

// ---------------------------------------------------------------------------
extern "C" void kernel_launch(void* const* d_in, const int* in_sizes, int n_in,
                              void* d_out, int out_size)
{
    const float* q  = (const float*)d_in[0];
    const float* k  = (const float*)d_in[1];
    const float* v  = (const float*)d_in[2];
    const float* wk = (const float*)d_in[3];
    const float* wv = (const float*)d_in[4];
    const float* wg = (const float*)d_in[5];
    float* out = (float*)d_out;

    compress_kernel<<<HKV * SC_N, NTHREADS>>>(k, v, wk, wv);

    const size_t smem_floats = 8 * 64 + 8 * 512 + 64 * 68 + 16 * 512 + 8 * 64 + 128 + 24;
    const size_t smem_bytes  = smem_floats * sizeof(float) + 8 * sizeof(int);
    cudaFuncSetAttribute(nsa_mega_kernel,
                         cudaFuncAttributeMaxDynamicSharedMemorySize, (int)smem_bytes);
    nsa_mega_kernel<<<S_LEN * HKV, NTHREADS, smem_bytes>>>(q, k, v, wg, out);
}